// round 15
// baseline (speedup 1.0000x reference)
#include <cuda_runtime.h>
#include <cstdint>

#define MAXN 50000
#define D 64
#define CAP 64   // per-node bucket capacity; in-degree ~ Poisson(16), P(>64) ~ 0
#define XP 68    // xa tile row pad (floats); mult of 4 (float4 rows)

// Scratch (device globals)
__device__ int    g_cnt[MAXN];
__device__ int    g_scol[MAXN * CAP];
__device__ float4 g_yn4[MAXN * (D / 4)];   // yn = x @ Wn^T (pre-aggregation)

// packed f32x2 FMA: d = a*b + d
__device__ __forceinline__ void fma2(unsigned long long& acc,
                                     unsigned long long a, unsigned long long b) {
    asm("fma.rn.f32x2 %0, %1, %2, %0;" : "+l"(acc) : "l"(a), "l"(b));
}
__device__ __forceinline__ float sum2(unsigned long long v) {
    return __uint_as_float((unsigned)v) + __uint_as_float((unsigned)(v >> 32));
}

// ---------------------------------------------------------------------------
// K1: bucket fill — single preprocessing pass (main stream).
// ---------------------------------------------------------------------------
__global__ __launch_bounds__(256) void bucket_fill_kernel(const int* __restrict__ ei,
                                                          int E, int N) {
    int e = blockIdx.x * 256 + threadIdx.x;
    if (e >= E) return;
    int r = min(max(__ldg(ei + e), 0), N - 1);
    int c = min(max(__ldg(ei + E + e), 0), N - 1);
    int pos = atomicAdd(&g_cnt[r], 1);
    if (pos < CAP) g_scol[r * CAP + pos] = c;
}

// ---------------------------------------------------------------------------
// Single-matrix GEMM body (f32x2 over K, LDS.128 weights/activations).
// Computes y[n][o] = sum_k x[n][k]*W[o][k] (+ optional bias via caller).
// Per thread: 4 nodes x 4 outs = 16 ULL accs. Weight smem [kp][2o+t].
// Thread outputs {2to, 2to+1, 2to+32, 2to+33}; w fetch = 1 LDS.128 per
// 2 outputs; a fetch = LDS.128 spanning kp,kp+1.
// ---------------------------------------------------------------------------
template <bool ADD_BIAS>
__device__ __forceinline__ void gemm_one(
    const float* __restrict__ x, const float* __restrict__ W,
    const float* __restrict__ b1, const float* __restrict__ b2,
    float* __restrict__ y, int N, float* sh)
{
    float* Wp   = sh;                 // [32][128]
    float* xa   = sh + 32 * 128;      // [64][XP]
    float* bias = sh + 32 * 128 + 64 * XP;  // [64]

    const int tid = threadIdx.x;
    const float4* x4 = reinterpret_cast<const float4*>(x);

    for (int i = tid; i < 64 * 64; i += 256) {
        int o = i >> 6, k = i & 63;
        Wp[(k >> 1) * 128 + 2 * o + (k & 1)] = W[i];
    }
    if (ADD_BIAS && tid < 64) bias[tid] = b1[tid] + b2[tid];

    const int node0 = blockIdx.x << 6;
    for (int i = tid; i < 64 * 16; i += 256) {
        int n = i >> 4, k4 = i & 15;
        int node = node0 + n;
        float4 v = (node < N) ? __ldg(x4 + (size_t)node * 16 + k4)
                              : make_float4(0.f, 0.f, 0.f, 0.f);
        *reinterpret_cast<float4*>(&xa[n * XP + 4 * k4]) = v;
    }
    __syncthreads();

    const int to = tid & 15;
    const int tn = tid >> 4;

    const ulonglong2* xa16 = reinterpret_cast<const ulonglong2*>(xa);
    const ulonglong2* Wv   = reinterpret_cast<const ulonglong2*>(Wp);

    unsigned long long acc[4][4];
    #pragma unroll
    for (int i = 0; i < 4; i++)
        #pragma unroll
        for (int j = 0; j < 4; j++) acc[i][j] = 0ULL;

    #pragma unroll 4
    for (int kp2 = 0; kp2 < 16; kp2++) {
        ulonglong2 a8[4];
        #pragma unroll
        for (int i = 0; i < 4; i++)
            a8[i] = xa16[(4 * tn + i) * (XP / 4) + kp2];

        #pragma unroll
        for (int kk = 0; kk < 2; kk++) {
            const int kp = 2 * kp2 + kk;
            ulonglong2 wa = Wv[kp * 32 + to];        // outs 2to, 2to+1
            ulonglong2 wb = Wv[kp * 32 + to + 16];   // outs 2to+32, 2to+33
            #pragma unroll
            for (int i = 0; i < 4; i++) {
                unsigned long long a = kk ? a8[i].y : a8[i].x;
                fma2(acc[i][0], a, wa.x); fma2(acc[i][1], a, wa.y);
                fma2(acc[i][2], a, wb.x); fma2(acc[i][3], a, wb.y);
            }
        }
    }

    const int oA = 2 * to;
    const int oB = 2 * to + 32;
    float2 bA = make_float2(0.f, 0.f), bB = make_float2(0.f, 0.f);
    if (ADD_BIAS) {
        bA = make_float2(bias[oA], bias[oA + 1]);
        bB = make_float2(bias[oB], bias[oB + 1]);
    }

    #pragma unroll
    for (int i = 0; i < 4; i++) {
        int node = node0 + 4 * tn + i;
        if (node < N) {
            size_t rowo = (size_t)node * D;
            float2 r;
            r.x = sum2(acc[i][0]) + bA.x; r.y = sum2(acc[i][1]) + bA.y;
            *reinterpret_cast<float2*>(&y[rowo + oA]) = r;
            r.x = sum2(acc[i][2]) + bB.x; r.y = sum2(acc[i][3]) + bB.y;
            *reinterpret_cast<float2*>(&y[rowo + oB]) = r;
        }
    }
}

// K2a (side): out = x @ Ws^T + (bs+bn)
__global__ __launch_bounds__(256, 3) void self_gemm_kernel(
    const float* __restrict__ x, const float* __restrict__ Ws,
    const float* __restrict__ bs, const float* __restrict__ bn,
    float* __restrict__ out, int N)
{
    extern __shared__ float sh[];
    gemm_one<true>(x, Ws, bs, bn, out, N, sh);
}

// K2b (side): yn = x @ Wn^T
__global__ __launch_bounds__(256, 3) void yn_gemm_kernel(
    const float* __restrict__ x, const float* __restrict__ Wn, int N)
{
    extern __shared__ float sh[];
    gemm_one<false>(x, Wn, nullptr, nullptr,
                    reinterpret_cast<float*>(g_yn4), N, sh);
}

// ---------------------------------------------------------------------------
// K3 (main stream, after join): gather over yn with fused epilogue:
//   out[n] += (sum_{c in bucket(n)} yn[c]) / max(deg,1)
// ---------------------------------------------------------------------------
__global__ __launch_bounds__(256) void gather_final_kernel(float* __restrict__ out,
                                                           int N) {
    int warp = (blockIdx.x * blockDim.x + threadIdx.x) >> 5;
    int lane = threadIdx.x & 31;
    if (warp >= N) return;

    const int cntv = g_cnt[warp];
    const int cnt  = min(cntv, CAP);
    const int slot = lane & 15;
    const int half = lane >> 4;
    const int* bucket = g_scol + warp * CAP;

    float4 acc = make_float4(0.f, 0.f, 0.f, 0.f);
    for (int j = half; j < cnt; j += 2) {
        int c = __ldg(bucket + j);
        float4 v = __ldg(reinterpret_cast<const float4*>(g_yn4) + (size_t)c * 16 + slot);
        acc.x += v.x; acc.y += v.y; acc.z += v.z; acc.w += v.w;
    }
    acc.x += __shfl_xor_sync(0xffffffff, acc.x, 16);
    acc.y += __shfl_xor_sync(0xffffffff, acc.y, 16);
    acc.z += __shfl_xor_sync(0xffffffff, acc.z, 16);
    acc.w += __shfl_xor_sync(0xffffffff, acc.w, 16);

    if (half == 0) {
        float inv = 1.0f / fmaxf((float)cntv, 1.0f);
        float4* p = reinterpret_cast<float4*>(out) + (size_t)warp * 16 + slot;
        float4 cur = *p;
        cur.x += acc.x * inv;
        cur.y += acc.y * inv;
        cur.z += acc.z * inv;
        cur.w += acc.w * inv;
        *p = cur;
    }
}

// ---------------------------------------------------------------------------
// Launch: fork/join. Side = yn GEMM then self GEMM (overlap fill).
// Main = memset -> fill -> (wait side) -> gather_final.
// ---------------------------------------------------------------------------
extern "C" void kernel_launch(void* const* d_in, const int* in_sizes, int n_in,
                              void* d_out, int out_size) {
    const float* x  = (const float*)d_in[0];
    const int*   ei = (const int*)d_in[1];   // int64 reference -> int32 on device
    const float* Ws = (const float*)d_in[2];
    const float* bs = (const float*)d_in[3];
    const float* Wn = (const float*)d_in[4];
    const float* bn = (const float*)d_in[5];
    float*       out = (float*)d_out;

    const int N = in_sizes[0] / D;
    const int E = in_sizes[1] / 2;

    // lazy one-time host resources (no device memory)
    static cudaStream_t sSide = nullptr;
    static cudaEvent_t  evFork = nullptr, evJoin = nullptr;
    static bool attrsSet = false;
    if (sSide == nullptr) {
        cudaStreamCreateWithFlags(&sSide, cudaStreamNonBlocking);
        cudaEventCreateWithFlags(&evFork, cudaEventDisableTiming);
        cudaEventCreateWithFlags(&evJoin, cudaEventDisableTiming);
    }

    const int smemG = (32 * 128 + 64 * XP + 64) * (int)sizeof(float);  // 34048 B
    if (!attrsSet) {
        cudaFuncSetAttribute(self_gemm_kernel,
                             cudaFuncAttributeMaxDynamicSharedMemorySize, smemG);
        cudaFuncSetAttribute(yn_gemm_kernel,
                             cudaFuncAttributeMaxDynamicSharedMemorySize, smemG);
        attrsSet = true;
    }

    // 0) zero bucket counters (main stream)
    void* cnt_ptr = nullptr;
    cudaGetSymbolAddress(&cnt_ptr, g_cnt);
    cudaMemsetAsync(cnt_ptr, 0, (size_t)N * sizeof(int));

    // fork: side stream runs both GEMMs (yn first, then self+bias)
    cudaEventRecord(evFork, 0);
    cudaStreamWaitEvent(sSide, evFork, 0);
    const int nTiles = (N + 63) / 64;
    yn_gemm_kernel<<<nTiles, 256, smemG, sSide>>>(x, Wn, N);
    self_gemm_kernel<<<nTiles, 256, smemG, sSide>>>(x, Ws, bs, bn, out, N);
    cudaEventRecord(evJoin, sSide);

    // main: bucket fill
    bucket_fill_kernel<<<(E + 255) / 256, 256>>>(ei, E, N);

    // join, then final gather accumulates normalized neighbor term into out
    cudaStreamWaitEvent(0, evJoin, 0);
    gather_final_kernel<<<(N * 32 + 255) / 256, 256>>>(out, N);
}

// round 16
// speedup vs baseline: 1.0005x; 1.0005x over previous
#include <cuda_runtime.h>
#include <cstdint>

#define MAXN 50000
#define D 64
#define CAP 64   // per-node bucket capacity; in-degree ~ Poisson(16), P(>64) ~ 0
#define XP 68    // xa tile row pad (floats); mult of 4 (float4 rows)

// Scratch (device globals)
__device__ int    g_cnt[MAXN];
__device__ int    g_scol[MAXN * CAP];
__device__ float4 g_yn4[MAXN * (D / 4)];   // yn = x @ Wn^T (pre-aggregation)
__device__ float4 g_nt4[MAXN * (D / 4)];   // normalized neighbor term

// packed f32x2 FMA: d = a*b + d
__device__ __forceinline__ void fma2(unsigned long long& acc,
                                     unsigned long long a, unsigned long long b) {
    asm("fma.rn.f32x2 %0, %1, %2, %0;" : "+l"(acc) : "l"(a), "l"(b));
}
__device__ __forceinline__ float sum2(unsigned long long v) {
    return __uint_as_float((unsigned)v) + __uint_as_float((unsigned)(v >> 32));
}

// ---------------------------------------------------------------------------
// K1: bucket fill — single preprocessing pass (main stream).
// ---------------------------------------------------------------------------
__global__ __launch_bounds__(256) void bucket_fill_kernel(const int* __restrict__ ei,
                                                          int E, int N) {
    int e = blockIdx.x * 256 + threadIdx.x;
    if (e >= E) return;
    int r = min(max(__ldg(ei + e), 0), N - 1);
    int c = min(max(__ldg(ei + E + e), 0), N - 1);
    int pos = atomicAdd(&g_cnt[r], 1);
    if (pos < CAP) g_scol[r * CAP + pos] = c;
}

// ---------------------------------------------------------------------------
// Single-matrix GEMM body (f32x2 over K, LDS.128 operands).
//   y[n][o] = sum_k x[n][k]*W[o][k] (+ bias if ADD_BIAS)
// ---------------------------------------------------------------------------
template <bool ADD_BIAS>
__device__ __forceinline__ void gemm_one(
    const float* __restrict__ x, const float* __restrict__ W,
    const float* __restrict__ b1, const float* __restrict__ b2,
    float* __restrict__ y, int N, float* sh)
{
    float* Wp   = sh;                 // [32][128]: W as [kp][2o+t]
    float* xa   = sh + 32 * 128;      // [64][XP] node-major x tile
    float* bias = sh + 32 * 128 + 64 * XP;  // [64]

    const int tid = threadIdx.x;
    const float4* x4 = reinterpret_cast<const float4*>(x);

    for (int i = tid; i < 64 * 64; i += 256) {
        int o = i >> 6, k = i & 63;
        Wp[(k >> 1) * 128 + 2 * o + (k & 1)] = W[i];
    }
    if (ADD_BIAS && tid < 64) bias[tid] = b1[tid] + b2[tid];

    const int node0 = blockIdx.x << 6;
    for (int i = tid; i < 64 * 16; i += 256) {
        int n = i >> 4, k4 = i & 15;
        int node = node0 + n;
        float4 v = (node < N) ? __ldg(x4 + (size_t)node * 16 + k4)
                              : make_float4(0.f, 0.f, 0.f, 0.f);
        *reinterpret_cast<float4*>(&xa[n * XP + 4 * k4]) = v;
    }
    __syncthreads();

    const int to = tid & 15;
    const int tn = tid >> 4;

    const ulonglong2* xa16 = reinterpret_cast<const ulonglong2*>(xa);
    const ulonglong2* Wv   = reinterpret_cast<const ulonglong2*>(Wp);

    unsigned long long acc[4][4];
    #pragma unroll
    for (int i = 0; i < 4; i++)
        #pragma unroll
        for (int j = 0; j < 4; j++) acc[i][j] = 0ULL;

    #pragma unroll 4
    for (int kp2 = 0; kp2 < 16; kp2++) {
        ulonglong2 a8[4];
        #pragma unroll
        for (int i = 0; i < 4; i++)
            a8[i] = xa16[(4 * tn + i) * (XP / 4) + kp2];

        #pragma unroll
        for (int kk = 0; kk < 2; kk++) {
            const int kp = 2 * kp2 + kk;
            ulonglong2 wa = Wv[kp * 32 + to];        // outs 2to, 2to+1
            ulonglong2 wb = Wv[kp * 32 + to + 16];   // outs 2to+32, 2to+33
            #pragma unroll
            for (int i = 0; i < 4; i++) {
                unsigned long long a = kk ? a8[i].y : a8[i].x;
                fma2(acc[i][0], a, wa.x); fma2(acc[i][1], a, wa.y);
                fma2(acc[i][2], a, wb.x); fma2(acc[i][3], a, wb.y);
            }
        }
    }

    const int oA = 2 * to;
    const int oB = 2 * to + 32;
    float2 bA = make_float2(0.f, 0.f), bB = make_float2(0.f, 0.f);
    if (ADD_BIAS) {
        bA = make_float2(bias[oA], bias[oA + 1]);
        bB = make_float2(bias[oB], bias[oB + 1]);
    }

    #pragma unroll
    for (int i = 0; i < 4; i++) {
        int node = node0 + 4 * tn + i;
        if (node < N) {
            size_t rowo = (size_t)node * D;
            float2 r;
            r.x = sum2(acc[i][0]) + bA.x; r.y = sum2(acc[i][1]) + bA.y;
            *reinterpret_cast<float2*>(&y[rowo + oA]) = r;
            r.x = sum2(acc[i][2]) + bB.x; r.y = sum2(acc[i][3]) + bB.y;
            *reinterpret_cast<float2*>(&y[rowo + oB]) = r;
        }
    }
}

// K2a (side, first): yn = x @ Wn^T  — gates the gather
__global__ __launch_bounds__(256, 3) void yn_gemm_kernel(
    const float* __restrict__ x, const float* __restrict__ Wn, int N)
{
    extern __shared__ float sh[];
    gemm_one<false>(x, Wn, nullptr, nullptr,
                    reinterpret_cast<float*>(g_yn4), N, sh);
}

// K2b (side, second): out = x @ Ws^T + (bs+bn) — overlaps the gather
__global__ __launch_bounds__(256, 3) void self_gemm_kernel(
    const float* __restrict__ x, const float* __restrict__ Ws,
    const float* __restrict__ bs, const float* __restrict__ bn,
    float* __restrict__ out, int N)
{
    extern __shared__ float sh[];
    gemm_one<true>(x, Ws, bs, bn, out, N, sh);
}

// ---------------------------------------------------------------------------
// K3 (main): gather over yn into the separate nt buffer (normalized):
//   nt[n] = (sum_{c in bucket(n)} yn[c]) / max(deg,1)
// ---------------------------------------------------------------------------
__global__ __launch_bounds__(256) void gather_nt_kernel(int N) {
    int warp = (blockIdx.x * blockDim.x + threadIdx.x) >> 5;
    int lane = threadIdx.x & 31;
    if (warp >= N) return;

    const int cntv = g_cnt[warp];
    const int cnt  = min(cntv, CAP);
    const int slot = lane & 15;
    const int half = lane >> 4;
    const int* bucket = g_scol + warp * CAP;

    float4 acc = make_float4(0.f, 0.f, 0.f, 0.f);
    for (int j = half; j < cnt; j += 2) {
        int c = __ldg(bucket + j);
        float4 v = __ldg(reinterpret_cast<const float4*>(g_yn4) + (size_t)c * 16 + slot);
        acc.x += v.x; acc.y += v.y; acc.z += v.z; acc.w += v.w;
    }
    acc.x += __shfl_xor_sync(0xffffffff, acc.x, 16);
    acc.y += __shfl_xor_sync(0xffffffff, acc.y, 16);
    acc.z += __shfl_xor_sync(0xffffffff, acc.z, 16);
    acc.w += __shfl_xor_sync(0xffffffff, acc.w, 16);

    if (half == 0) {
        float inv = 1.0f / fmaxf((float)cntv, 1.0f);
        acc.x *= inv; acc.y *= inv; acc.z *= inv; acc.w *= inv;
        g_nt4[(size_t)warp * 16 + slot] = acc;
    }
}

// ---------------------------------------------------------------------------
// K4 (main, after both): out += nt  (pure streaming add)
// ---------------------------------------------------------------------------
__global__ __launch_bounds__(256) void combine_kernel(float* __restrict__ out, int N) {
    int i = blockIdx.x * 256 + threadIdx.x;
    int n4 = N * 16;
    if (i < n4) {
        float4 a = reinterpret_cast<float4*>(out)[i];
        float4 b = g_nt4[i];
        a.x += b.x; a.y += b.y; a.z += b.z; a.w += b.w;
        reinterpret_cast<float4*>(out)[i] = a;
    }
}

// ---------------------------------------------------------------------------
// Launch DAG:
//   side: yn_gemm [evYn] -> self_gemm [evSelf]
//   main: memset -> fill -> wait(evYn) -> gather_nt -> wait(evSelf) -> combine
// ---------------------------------------------------------------------------
extern "C" void kernel_launch(void* const* d_in, const int* in_sizes, int n_in,
                              void* d_out, int out_size) {
    const float* x  = (const float*)d_in[0];
    const int*   ei = (const int*)d_in[1];   // int64 reference -> int32 on device
    const float* Ws = (const float*)d_in[2];
    const float* bs = (const float*)d_in[3];
    const float* Wn = (const float*)d_in[4];
    const float* bn = (const float*)d_in[5];
    float*       out = (float*)d_out;

    const int N = in_sizes[0] / D;
    const int E = in_sizes[1] / 2;

    // lazy one-time host resources (no device memory)
    static cudaStream_t sSide = nullptr;
    static cudaEvent_t  evFork = nullptr, evYn = nullptr, evSelf = nullptr;
    static bool attrsSet = false;
    if (sSide == nullptr) {
        cudaStreamCreateWithFlags(&sSide, cudaStreamNonBlocking);
        cudaEventCreateWithFlags(&evFork, cudaEventDisableTiming);
        cudaEventCreateWithFlags(&evYn,   cudaEventDisableTiming);
        cudaEventCreateWithFlags(&evSelf, cudaEventDisableTiming);
    }

    const int smemG = (32 * 128 + 64 * XP + 64) * (int)sizeof(float);  // 34048 B
    if (!attrsSet) {
        cudaFuncSetAttribute(self_gemm_kernel,
                             cudaFuncAttributeMaxDynamicSharedMemorySize, smemG);
        cudaFuncSetAttribute(yn_gemm_kernel,
                             cudaFuncAttributeMaxDynamicSharedMemorySize, smemG);
        attrsSet = true;
    }

    // 0) zero bucket counters (main stream)
    void* cnt_ptr = nullptr;
    cudaGetSymbolAddress(&cnt_ptr, g_cnt);
    cudaMemsetAsync(cnt_ptr, 0, (size_t)N * sizeof(int));

    // fork side stream
    cudaEventRecord(evFork, 0);
    cudaStreamWaitEvent(sSide, evFork, 0);

    const int nTiles = (N + 63) / 64;
    // side: yn first (gates gather), then self (overlaps gather)
    yn_gemm_kernel<<<nTiles, 256, smemG, sSide>>>(x, Wn, N);
    cudaEventRecord(evYn, sSide);
    self_gemm_kernel<<<nTiles, 256, smemG, sSide>>>(x, Ws, bs, bn, out, N);
    cudaEventRecord(evSelf, sSide);

    // main: bucket fill (overlaps yn)
    bucket_fill_kernel<<<(E + 255) / 256, 256>>>(ei, E, N);

    // main: gather (needs yn + buckets), runs concurrent with self
    cudaStreamWaitEvent(0, evYn, 0);
    gather_nt_kernel<<<(N * 32 + 255) / 256, 256>>>(N);

    // main: combine after self finished
    cudaStreamWaitEvent(0, evSelf, 0);
    combine_kernel<<<(N * 16 + 255) / 256, 256>>>(out, N);
}